// round 2
// baseline (speedup 1.0000x reference)
#include <cuda_runtime.h>
#include <math_constants.h>

// Output = one-hot(argmax over F of logits+gumbel); forward-exact vs reference
// (straight-through mask is numerically one-hot; top-K-smallest zeroing hits
//  only entries that are already exactly 0).
//
// Persistent-grid version: exactly one wave of CTAs (148 SMs x 8 blocks),
// each warp grid-strides over rows. Removes wave-transition bubbles and lets
// ptxas hoist the next row's (independent) loads above the current row's
// shuffle reduction, keeping MLP high. Streaming cache hints since no line
// is ever reused.

static constexpr int Bc = 32;
static constexpr int Sc = 2048;
static constexpr int Fc = 512;
static constexpr int ROWS = Bc * Sc;          // 65536 rows
static constexpr int F4  = Fc / 4;            // 128 float4 per row

static constexpr int SMS            = 148;
static constexpr int BLOCKS_PER_SM  = 8;      // 8 x 256 thr = 64 warps/SM (occ cap)
static constexpr int THREADS        = 256;
static constexpr int GRID           = SMS * BLOCKS_PER_SM;     // 1184 blocks
static constexpr int TOTAL_WARPS    = GRID * (THREADS / 32);   // 9472 warps

__global__ __launch_bounds__(THREADS)
void onehot_argmax_kernel(const float4* __restrict__ logits,
                          const float4* __restrict__ gumbel,
                          float4* __restrict__ out) {
    const int warp0 = (blockIdx.x * THREADS + threadIdx.x) >> 5;
    const int lane  = threadIdx.x & 31;

    for (int row = warp0; row < ROWS; row += TOTAL_WARPS) {
        const size_t base = (size_t)row * F4;

        float best = -CUDART_INF_F;
        int   bidx = 0;

        // Each lane: 4 float4 per input, positions c*32+lane. Indices strictly
        // increase within a lane, so strict ">" gives first-index tie-break
        // per lane; cross-lane tie-break handled in the butterfly.
        #pragma unroll
        for (int c = 0; c < 4; c++) {
            const int p = c * 32 + lane;
            const float4 a = __ldcs(&logits[base + p]);
            const float4 g = __ldcs(&gumbel[base + p]);
            const float s0 = a.x + g.x;
            const float s1 = a.y + g.y;
            const float s2 = a.z + g.z;
            const float s3 = a.w + g.w;
            const int e = p * 4;
            if (s0 > best) { best = s0; bidx = e;     }
            if (s1 > best) { best = s1; bidx = e + 1; }
            if (s2 > best) { best = s2; bidx = e + 2; }
            if (s3 > best) { best = s3; bidx = e + 3; }
        }

        // Butterfly: max by value, lowest index on ties (== jnp.argmax).
        // Associative + commutative lexicographic max -> all lanes converge.
        #pragma unroll
        for (int off = 16; off; off >>= 1) {
            const float ov = __shfl_xor_sync(0xffffffffu, best, off);
            const int   oi = __shfl_xor_sync(0xffffffffu, bidx, off);
            if (ov > best || (ov == best && oi < bidx)) { best = ov; bidx = oi; }
        }

        // Compose + stream out the one-hot row (no RMW; evict-first stores).
        #pragma unroll
        for (int c = 0; c < 4; c++) {
            const int p = c * 32 + lane;
            const int e = p * 4;
            float4 o;
            o.x = (e     == bidx) ? 1.0f : 0.0f;
            o.y = (e + 1 == bidx) ? 1.0f : 0.0f;
            o.z = (e + 2 == bidx) ? 1.0f : 0.0f;
            o.w = (e + 3 == bidx) ? 1.0f : 0.0f;
            __stcs(&out[base + p], o);
        }
    }
}

extern "C" void kernel_launch(void* const* d_in, const int* in_sizes, int n_in,
                              void* d_out, int out_size) {
    const float4* logits = (const float4*)d_in[0];
    const float4* gumbel = (const float4*)d_in[1];
    float4* out = (float4*)d_out;

    onehot_argmax_kernel<<<GRID, THREADS>>>(logits, gumbel, out);
}

// round 3
// speedup vs baseline: 1.0594x; 1.0594x over previous
#include <cuda_runtime.h>
#include <math_constants.h>

// Output = one-hot(argmax over F of logits+gumbel); forward-exact vs reference
// (straight-through mask is numerically one-hot; the top-K-smallest zeroing
//  only touches entries that are already exactly 0).
//
// R3 = R1 (one warp per row, 8192 blocks) + __launch_bounds__(256, 8):
// forces 32 regs/thread -> 64 resident warps/SM (vs 48 at the 40-reg tier),
// raising in-flight LDG count and DRAM duty cycle. Single-variable change
// vs the 52.2us R1 kernel.

static constexpr int Bc = 32;
static constexpr int Sc = 2048;
static constexpr int Fc = 512;
static constexpr int ROWS = Bc * Sc;          // 65536 rows
static constexpr int F4  = Fc / 4;            // 128 float4 per row

__global__ __launch_bounds__(256, 8)
void onehot_argmax_kernel(const float4* __restrict__ logits,
                          const float4* __restrict__ gumbel,
                          float4* __restrict__ out) {
    const int warp = (blockIdx.x * blockDim.x + threadIdx.x) >> 5;
    const int lane = threadIdx.x & 31;
    if (warp >= ROWS) return;

    const size_t base = (size_t)warp * F4;

    float best = -CUDART_INF_F;
    int   bidx = 0;

    // Each lane handles 4 float4s: positions c*32 + lane (c = 0..3).
    // Indices strictly increase within a lane, so strict ">" gives the
    // first-index tie-break per lane; cross-lane tie-break in the butterfly.
    #pragma unroll
    for (int c = 0; c < 4; c++) {
        const int p = c * 32 + lane;
        const float4 a = logits[base + p];
        const float4 g = gumbel[base + p];
        const float s0 = a.x + g.x;
        const float s1 = a.y + g.y;
        const float s2 = a.z + g.z;
        const float s3 = a.w + g.w;
        const int e = p * 4;
        if (s0 > best) { best = s0; bidx = e;     }
        if (s1 > best) { best = s1; bidx = e + 1; }
        if (s2 > best) { best = s2; bidx = e + 2; }
        if (s3 > best) { best = s3; bidx = e + 3; }
    }

    // Butterfly reduction: max by value, lowest index on ties (== jnp.argmax).
    // Lexicographic max is associative+commutative, so all lanes converge to
    // the row argmax -- no broadcast needed before the store phase.
    #pragma unroll
    for (int off = 16; off; off >>= 1) {
        const float ov = __shfl_xor_sync(0xffffffffu, best, off);
        const int   oi = __shfl_xor_sync(0xffffffffu, bidx, off);
        if (ov > best || (ov == best && oi < bidx)) { best = ov; bidx = oi; }
    }

    // Compose + write the one-hot row (each lane owns its float4s; no RMW).
    #pragma unroll
    for (int c = 0; c < 4; c++) {
        const int p = c * 32 + lane;
        const int e = p * 4;
        float4 o;
        o.x = (e     == bidx) ? 1.0f : 0.0f;
        o.y = (e + 1 == bidx) ? 1.0f : 0.0f;
        o.z = (e + 2 == bidx) ? 1.0f : 0.0f;
        o.w = (e + 3 == bidx) ? 1.0f : 0.0f;
        out[base + p] = o;
    }
}

extern "C" void kernel_launch(void* const* d_in, const int* in_sizes, int n_in,
                              void* d_out, int out_size) {
    const float4* logits = (const float4*)d_in[0];
    const float4* gumbel = (const float4*)d_in[1];
    float4* out = (float4*)d_out;

    const int threads = 256;
    const int warps_per_block = threads / 32;
    const int blocks = (ROWS + warps_per_block - 1) / warps_per_block;  // 8192
    onehot_argmax_kernel<<<blocks, threads>>>(logits, gumbel, out);
}

// round 4
// speedup vs baseline: 1.0599x; 1.0005x over previous
#include <cuda_runtime.h>
#include <math_constants.h>

// Output = one-hot(argmax over F of logits+gumbel); forward-exact vs reference
// (straight-through mask is numerically one-hot; the top-K-smallest zeroing
//  only touches entries that are already exactly 0).
//
// R4 = R1 launch shape (one warp per row, 8192 x 256, natural regs) with the
// 8 LDG.128s front-batched into registers before any arithmetic: maximizes
// per-warp MLP (the binding resource per R2/R3 evidence: low-occ high-MLP
// beat high-occ low-MLP).

static constexpr int Bc = 32;
static constexpr int Sc = 2048;
static constexpr int Fc = 512;
static constexpr int ROWS = Bc * Sc;          // 65536 rows
static constexpr int F4  = Fc / 4;            // 128 float4 per row

__global__ __launch_bounds__(256)
void onehot_argmax_kernel(const float4* __restrict__ logits,
                          const float4* __restrict__ gumbel,
                          float4* __restrict__ out) {
    const int warp = (blockIdx.x * blockDim.x + threadIdx.x) >> 5;
    const int lane = threadIdx.x & 31;
    if (warp >= ROWS) return;

    const size_t base = (size_t)warp * F4;
    const float4* __restrict__ lp = logits + base + lane;
    const float4* __restrict__ gp = gumbel + base + lane;

    // Front-batch ALL loads: 8 independent LDG.128 in flight (MLP=8/warp)
    // before a single FADD issues.
    float4 a0 = lp[0];
    float4 a1 = lp[32];
    float4 a2 = lp[64];
    float4 a3 = lp[96];
    float4 g0 = gp[0];
    float4 g1 = gp[32];
    float4 g2 = gp[64];
    float4 g3 = gp[96];

    float best = -CUDART_INF_F;
    int   bidx = 0;

    // Within a lane the element indices are strictly increasing, so strict ">"
    // gives first-index tie-break per lane; cross-lane tie-break in butterfly.
    {
        const int e = (0 * 32 + lane) * 4;
        float s;
        s = a0.x + g0.x; if (s > best) { best = s; bidx = e;     }
        s = a0.y + g0.y; if (s > best) { best = s; bidx = e + 1; }
        s = a0.z + g0.z; if (s > best) { best = s; bidx = e + 2; }
        s = a0.w + g0.w; if (s > best) { best = s; bidx = e + 3; }
    }
    {
        const int e = (1 * 32 + lane) * 4;
        float s;
        s = a1.x + g1.x; if (s > best) { best = s; bidx = e;     }
        s = a1.y + g1.y; if (s > best) { best = s; bidx = e + 1; }
        s = a1.z + g1.z; if (s > best) { best = s; bidx = e + 2; }
        s = a1.w + g1.w; if (s > best) { best = s; bidx = e + 3; }
    }
    {
        const int e = (2 * 32 + lane) * 4;
        float s;
        s = a2.x + g2.x; if (s > best) { best = s; bidx = e;     }
        s = a2.y + g2.y; if (s > best) { best = s; bidx = e + 1; }
        s = a2.z + g2.z; if (s > best) { best = s; bidx = e + 2; }
        s = a2.w + g2.w; if (s > best) { best = s; bidx = e + 3; }
    }
    {
        const int e = (3 * 32 + lane) * 4;
        float s;
        s = a3.x + g3.x; if (s > best) { best = s; bidx = e;     }
        s = a3.y + g3.y; if (s > best) { best = s; bidx = e + 1; }
        s = a3.z + g3.z; if (s > best) { best = s; bidx = e + 2; }
        s = a3.w + g3.w; if (s > best) { best = s; bidx = e + 3; }
    }

    // Butterfly: max by value, lowest index on ties (== jnp.argmax).
    // Lexicographic max is associative+commutative -> all lanes converge.
    #pragma unroll
    for (int off = 16; off; off >>= 1) {
        const float ov = __shfl_xor_sync(0xffffffffu, best, off);
        const int   oi = __shfl_xor_sync(0xffffffffu, bidx, off);
        if (ov > best || (ov == best && oi < bidx)) { best = ov; bidx = oi; }
    }

    // Compose + write the one-hot row (each lane owns its float4s; no RMW).
    float4* __restrict__ op = out + base + lane;
    #pragma unroll
    for (int c = 0; c < 4; c++) {
        const int e = (c * 32 + lane) * 4;
        float4 o;
        o.x = (e     == bidx) ? 1.0f : 0.0f;
        o.y = (e + 1 == bidx) ? 1.0f : 0.0f;
        o.z = (e + 2 == bidx) ? 1.0f : 0.0f;
        o.w = (e + 3 == bidx) ? 1.0f : 0.0f;
        op[c * 32] = o;
    }
}

extern "C" void kernel_launch(void* const* d_in, const int* in_sizes, int n_in,
                              void* d_out, int out_size) {
    const float4* logits = (const float4*)d_in[0];
    const float4* gumbel = (const float4*)d_in[1];
    float4* out = (float4*)d_out;

    const int threads = 256;
    const int warps_per_block = threads / 32;
    const int blocks = (ROWS + warps_per_block - 1) / warps_per_block;  // 8192
    onehot_argmax_kernel<<<blocks, threads>>>(logits, gumbel, out);
}